// round 13
// baseline (speedup 1.0000x reference)
#include <cuda_runtime.h>
#include <cuda_fp16.h>

// NeRF volume-rendering aggregation — R13.
// R12 failed to compile: redux.sync.add.f32 is NOT a thing on sm_103 (int-only).
// Replacements:
//  - alpha_map via telescoping identity: sum(alpha_i*T_i) = 1 - prod(all t)
//    (+eps*sum(T) ~ 1e-8, dropped). prod(all t) is free from the scan ->
//    one whole warp-reduce (5 SHFL + 5 FADD) deleted.
//  - grid = 148*6 = 888 EXACTLY: one resident wave (R9 ran 2 waves by mistake).
//  - weights stored with __stcs (evict-first; don't pollute L2 vs read stream).
// Base: R9 (depth-2 cp.async double buffer, f16x2 tanh, 40 regs, 6 blocks/SM).

#define FARV 1e10f
#define EPSV 1e-10f
#define FULL 0xffffffffu

__device__ __forceinline__ __half2 h2_tanh(__half2 x) {
    __half2 r;
    asm("tanh.approx.f16x2 %0, %1;" : "=r"(*(unsigned*)&r) : "r"(*(unsigned*)&x));
    return r;
}

// XOR-swizzle byte offset within a 2048B tile.
__device__ __forceinline__ unsigned swz(unsigned a) {
    return a ^ ((a >> 3) & 0x30u);
}

__device__ __forceinline__ void cpasync16(unsigned dst, const void* src) {
    asm volatile("cp.async.cg.shared.global [%0], [%1], 16;" :: "r"(dst), "l"(src));
}
__device__ __forceinline__ void cpcommit() {
    asm volatile("cp.async.commit_group;");
}
__device__ __forceinline__ void cpwait1() {
    asm volatile("cp.async.wait_group 1;");
}

__global__ __launch_bounds__(256, 6) void nerf_agg_kernel(
    const float4* __restrict__ raw,    // (NR, 128) of float4
    const float*  __restrict__ z,      // (NR, 128)
    const float*  __restrict__ rays_d, // (NR, 3)
    const float*  __restrict__ bg,     // (3)
    float* __restrict__ out_rgb,       // (NR, 3)
    float* __restrict__ out_depth,     // (NR)
    float* __restrict__ out_disp,      // (NR)
    float* __restrict__ out_alpha,     // (NR)
    float* __restrict__ out_w,         // (NR, 128)
    int nrays)
{
    __shared__ __align__(128) char sbuf[8 * 2 * 2048];  // per-warp double buffer

    const int warp = threadIdx.x >> 5;
    const int lane = threadIdx.x & 31;
    char* swp = sbuf + warp * 4096;
    const unsigned swb = (unsigned)__cvta_generic_to_shared(swp);

    const int gw = blockIdx.x * 8 + warp;     // global warp id
    const int W  = gridDim.x * 8;             // total warps (stride)
    if (gw >= nrays) return;                  // warp-uniform

    // loop-invariant background state
    const float b0 = bg[0], b1 = bg[1], b2 = bg[2];
    const bool is_bg = (b0 >= 0.f && b0 <= 1.f &&
                        b1 >= 0.f && b1 <= 1.f &&
                        b2 >= 0.f && b2 <= 1.f);

    // ---- prologue: prefetch ray gw into buffer 0; z/norm into registers ----
    {
        const float4* rawr = raw + (size_t)gw * 128;
#pragma unroll
        for (int rr = 0; rr < 4; rr++)
            cpasync16(swb + swz((rr * 32 + lane) * 16u), rawr + rr * 32 + lane);
        cpcommit();
    }
    float4 zc = *(const float4*)(z + (size_t)gw * 128 + lane * 4);
    float nrmc;
    {
        const float a = rays_d[gw * 3 + 0];
        const float b = rays_d[gw * 3 + 1];
        const float c = rays_d[gw * 3 + 2];
        nrmc = sqrtf(a * a + b * b + c * c);
    }

    int buf = 0;
    for (int ray = gw; ray < nrays; ray += W) {
        // ---- prefetch next ray (flies during this ray's compute) ----
        const int nray = ray + W;
        float4 zn_c = zc;
        float  nrmn = nrmc;
        if (nray < nrays) {         // warp-uniform branch
            const float4* rawr = raw + (size_t)nray * 128;
            const unsigned d = swb + (unsigned)(buf ^ 1) * 2048u;
#pragma unroll
            for (int rr = 0; rr < 4; rr++)
                cpasync16(d + swz((rr * 32 + lane) * 16u), rawr + rr * 32 + lane);
            zn_c = *(const float4*)(z + (size_t)nray * 128 + lane * 4);
            const float a = rays_d[nray * 3 + 0];
            const float b = rays_d[nray * 3 + 1];
            const float c = rays_d[nray * 3 + 2];
            nrmn = sqrtf(a * a + b * b + c * c);
        }
        cpcommit();                 // one group per iteration (may be empty)
        cpwait1();                  // current buffer's group complete
        __syncwarp();

        // ---- read transposed points from smem ----
        char* d = swp + buf * 2048;
        float4 pt[4];
#pragma unroll
        for (int i = 0; i < 4; i++)
            pt[i] = *(const float4*)(d + swz((lane * 4 + i) * 16u));

        const float4 z4 = zc;
        const float  nrm = nrmc;

        // ---- z neighbors: lane-local except the lane boundary ----
        const float zb = __shfl_down_sync(FULL, z4.x, 1);    // z[lane*4+4]
        const float zloc[4] = { z4.x, z4.y, z4.z, z4.w };
        const float znxt[4] = { z4.y, z4.z, z4.w, zb };

        // ---- alpha + transmittance factors (f32 EX2) ----
        float alpha[4], t[4];
#pragma unroll
        for (int i = 0; i < 4; i++) {
            float dd = znxt[i] - zloc[i];
            if (i == 3 && lane == 31) dd = FARV;             // p == 127
            dd *= nrm;
            const float ex = __expf(-fmaxf(pt[i].w, 0.0f) * dd);
            alpha[i] = 1.0f - ex;
            t[i]     = ex + EPSV;                            // 1 - alpha + EPS
        }

        // ---- single warp scan over local products ----
        float S = (t[0] * t[1]) * (t[2] * t[3]);
#pragma unroll
        for (int off = 1; off < 32; off <<= 1) {
            const float v = __shfl_up_sync(FULL, S, off);
            S = (lane >= off) ? S * v : S;
        }
        const float Ptot = __shfl_sync(FULL, S, 31);         // product of ALL 128 t
        float E = __shfl_up_sync(FULL, S, 1);                // exclusive lane prefix
        if (lane == 0) E = 1.0f;

        const float e1 = E  * t[0];
        const float e2 = e1 * t[1];
        const float e3 = e2 * t[2];
        const float w0 = alpha[0] * E;
        const float w1 = alpha[1] * e1;
        const float w2 = alpha[2] * e2;
        const float w3 = alpha[3] * e3;

        // streaming store (evict-first): don't hold weights in L2
        __stcs((float4*)(out_w + (size_t)ray * 128 + lane * 4),
               make_float4(w0, w1, w2, w3));

        // ---- packed tanh; accumulate raw tanh dot-products ----
        const __half2 hx0 = h2_tanh(__floats2half2_rn(0.5f * pt[0].x, 0.5f * pt[1].x));
        const __half2 hy0 = h2_tanh(__floats2half2_rn(0.5f * pt[0].y, 0.5f * pt[1].y));
        const __half2 hz0 = h2_tanh(__floats2half2_rn(0.5f * pt[0].z, 0.5f * pt[1].z));
        const __half2 hx1 = h2_tanh(__floats2half2_rn(0.5f * pt[2].x, 0.5f * pt[3].x));
        const __half2 hy1 = h2_tanh(__floats2half2_rn(0.5f * pt[2].y, 0.5f * pt[3].y));
        const __half2 hz1 = h2_tanh(__floats2half2_rn(0.5f * pt[2].z, 0.5f * pt[3].z));

        float ar = fmaf(w0, __low2float (hx0),
                   fmaf(w1, __high2float(hx0),
                   fmaf(w2, __low2float (hx1), w3 * __high2float(hx1))));
        float ag = fmaf(w0, __low2float (hy0),
                   fmaf(w1, __high2float(hy0),
                   fmaf(w2, __low2float (hy1), w3 * __high2float(hy1))));
        float ab = fmaf(w0, __low2float (hz0),
                   fmaf(w1, __high2float(hz0),
                   fmaf(w2, __low2float (hz1), w3 * __high2float(hz1))));
        float ad = fmaf(w0, zloc[0], fmaf(w1, zloc[1], fmaf(w2, zloc[2], w3 * zloc[3])));

        // ---- 4 warp tree-reduces (aa comes free from the scan total) ----
#pragma unroll
        for (int off = 16; off >= 1; off >>= 1) {
            ar += __shfl_xor_sync(FULL, ar, off);
            ag += __shfl_xor_sync(FULL, ag, off);
            ab += __shfl_xor_sync(FULL, ab, off);
            ad += __shfl_xor_sync(FULL, ad, off);
        }

        // alpha_map = sum w = 1 - prod(all t)   (+eps*sum(T) ~ 1e-8, dropped)
        const float aa = 1.0f - Ptot;

        if (lane == 0) {
            // fold sigma = 0.5*tanh + 0.5
            float cr = fmaf(0.5f, ar, 0.5f * aa);
            float cg = fmaf(0.5f, ag, 0.5f * aa);
            float cb = fmaf(0.5f, ab, 0.5f * aa);

            if (is_bg) {
                const float m = 1.0f - aa;
                cr = fmaf(m, b0, cr);
                cg = fmaf(m, b1, cg);
                cb = fmaf(m, b2, cb);
            }
            out_rgb[ray * 3 + 0] = cr;
            out_rgb[ray * 3 + 1] = cg;
            out_rgb[ray * 3 + 2] = cb;
            out_depth[ray] = ad;
            out_alpha[ray] = aa;

            const float q = ad / aa;
            out_disp[ray] = 1.0f / (fmaxf(q - EPSV, 0.0f) + EPSV);
        }

        // ---- rotate pipeline ----
        zc   = zn_c;
        nrmc = nrmn;
        buf ^= 1;
    }
}

extern "C" void kernel_launch(void* const* d_in, const int* in_sizes, int n_in,
                              void* d_out, int out_size)
{
    const float* raw = (const float*)d_in[0];  // (B,R,P,4)
    const float* zv  = (const float*)d_in[1];  // (B,R,P)
    const float* rd  = (const float*)d_in[2];  // (B,R,3)
    const float* bg  = (const float*)d_in[3];  // (3)

    const int nrays = in_sizes[1] / 128;       // B*R

    float* out       = (float*)d_out;
    float* out_rgb   = out;
    float* out_depth = out + (size_t)nrays * 3;
    float* out_disp  = out + (size_t)nrays * 4;
    float* out_alpha = out + (size_t)nrays * 5;
    float* out_w     = out + (size_t)nrays * 6;

    int blocks = 148 * 6;                      // ONE resident wave @ 6 blocks/SM
    const int maxblk = (nrays + 7) / 8;
    if (blocks > maxblk) blocks = maxblk;
    nerf_agg_kernel<<<blocks, 256>>>((const float4*)raw, zv, rd, bg,
                                     out_rgb, out_depth, out_disp, out_alpha,
                                     out_w, nrays);
}

// round 15
// speedup vs baseline: 1.2762x; 1.2762x over previous
#include <cuda_runtime.h>
#include <cuda_fp16.h>

// NeRF volume-rendering aggregation — R14.
// R13 regressed 33.5->45.7us. Root cause: single persistent wave (grid 888)
// loses to 2-wave + scheduler backfill on tail imbalance (occ 55.7% < 75%
// theoretical; DRAM 51%). __stcs also suspect (write-combining).
// R14 = R9 config (grid 1776, depth-2 cp.async pipeline, 40 regs, 6/SM)
//       + aa-telescoping kept from R13 (alpha_map = 1 - prod(t): one fewer
//         warp reduce; rel_err unchanged 5.2519e-5).
//       + plain float4 weights store (no .cs hint).

#define FARV 1e10f
#define EPSV 1e-10f
#define FULL 0xffffffffu

__device__ __forceinline__ __half2 h2_tanh(__half2 x) {
    __half2 r;
    asm("tanh.approx.f16x2 %0, %1;" : "=r"(*(unsigned*)&r) : "r"(*(unsigned*)&x));
    return r;
}

// XOR-swizzle byte offset within a 2048B tile.
__device__ __forceinline__ unsigned swz(unsigned a) {
    return a ^ ((a >> 3) & 0x30u);
}

__device__ __forceinline__ void cpasync16(unsigned dst, const void* src) {
    asm volatile("cp.async.cg.shared.global [%0], [%1], 16;" :: "r"(dst), "l"(src));
}
__device__ __forceinline__ void cpcommit() {
    asm volatile("cp.async.commit_group;");
}
__device__ __forceinline__ void cpwait1() {
    asm volatile("cp.async.wait_group 1;");
}

__global__ __launch_bounds__(256, 6) void nerf_agg_kernel(
    const float4* __restrict__ raw,    // (NR, 128) of float4
    const float*  __restrict__ z,      // (NR, 128)
    const float*  __restrict__ rays_d, // (NR, 3)
    const float*  __restrict__ bg,     // (3)
    float* __restrict__ out_rgb,       // (NR, 3)
    float* __restrict__ out_depth,     // (NR)
    float* __restrict__ out_disp,      // (NR)
    float* __restrict__ out_alpha,     // (NR)
    float* __restrict__ out_w,         // (NR, 128)
    int nrays)
{
    __shared__ __align__(128) char sbuf[8 * 2 * 2048];  // per-warp double buffer

    const int warp = threadIdx.x >> 5;
    const int lane = threadIdx.x & 31;
    char* swp = sbuf + warp * 4096;
    const unsigned swb = (unsigned)__cvta_generic_to_shared(swp);

    const int gw = blockIdx.x * 8 + warp;     // global warp id
    const int W  = gridDim.x * 8;             // total warps (stride)
    if (gw >= nrays) return;                  // warp-uniform

    // loop-invariant background state
    const float b0 = bg[0], b1 = bg[1], b2 = bg[2];
    const bool is_bg = (b0 >= 0.f && b0 <= 1.f &&
                        b1 >= 0.f && b1 <= 1.f &&
                        b2 >= 0.f && b2 <= 1.f);

    // ---- prologue: prefetch ray gw into buffer 0; z/norm into registers ----
    {
        const float4* rawr = raw + (size_t)gw * 128;
#pragma unroll
        for (int rr = 0; rr < 4; rr++)
            cpasync16(swb + swz((rr * 32 + lane) * 16u), rawr + rr * 32 + lane);
        cpcommit();
    }
    float4 zc = *(const float4*)(z + (size_t)gw * 128 + lane * 4);
    float nrmc;
    {
        const float a = rays_d[gw * 3 + 0];
        const float b = rays_d[gw * 3 + 1];
        const float c = rays_d[gw * 3 + 2];
        nrmc = sqrtf(a * a + b * b + c * c);
    }

    int buf = 0;
    for (int ray = gw; ray < nrays; ray += W) {
        // ---- prefetch next ray (flies during this ray's compute) ----
        const int nray = ray + W;
        float4 zn_c = zc;
        float  nrmn = nrmc;
        if (nray < nrays) {         // warp-uniform branch
            const float4* rawr = raw + (size_t)nray * 128;
            const unsigned d = swb + (unsigned)(buf ^ 1) * 2048u;
#pragma unroll
            for (int rr = 0; rr < 4; rr++)
                cpasync16(d + swz((rr * 32 + lane) * 16u), rawr + rr * 32 + lane);
            zn_c = *(const float4*)(z + (size_t)nray * 128 + lane * 4);
            const float a = rays_d[nray * 3 + 0];
            const float b = rays_d[nray * 3 + 1];
            const float c = rays_d[nray * 3 + 2];
            nrmn = sqrtf(a * a + b * b + c * c);
        }
        cpcommit();                 // one group per iteration (may be empty)
        cpwait1();                  // current buffer's group complete
        __syncwarp();

        // ---- read transposed points from smem ----
        char* d = swp + buf * 2048;
        float4 pt[4];
#pragma unroll
        for (int i = 0; i < 4; i++)
            pt[i] = *(const float4*)(d + swz((lane * 4 + i) * 16u));

        const float4 z4 = zc;
        const float  nrm = nrmc;

        // ---- z neighbors: lane-local except the lane boundary ----
        const float zb = __shfl_down_sync(FULL, z4.x, 1);    // z[lane*4+4]
        const float zloc[4] = { z4.x, z4.y, z4.z, z4.w };
        const float znxt[4] = { z4.y, z4.z, z4.w, zb };

        // ---- alpha + transmittance factors (f32 EX2) ----
        float alpha[4], t[4];
#pragma unroll
        for (int i = 0; i < 4; i++) {
            float dd = znxt[i] - zloc[i];
            if (i == 3 && lane == 31) dd = FARV;             // p == 127
            dd *= nrm;
            const float ex = __expf(-fmaxf(pt[i].w, 0.0f) * dd);
            alpha[i] = 1.0f - ex;
            t[i]     = ex + EPSV;                            // 1 - alpha + EPS
        }

        // ---- single warp scan over local products ----
        float S = (t[0] * t[1]) * (t[2] * t[3]);
#pragma unroll
        for (int off = 1; off < 32; off <<= 1) {
            const float v = __shfl_up_sync(FULL, S, off);
            S = (lane >= off) ? S * v : S;
        }
        const float Ptot = __shfl_sync(FULL, S, 31);         // product of ALL 128 t
        float E = __shfl_up_sync(FULL, S, 1);                // exclusive lane prefix
        if (lane == 0) E = 1.0f;

        const float e1 = E  * t[0];
        const float e2 = e1 * t[1];
        const float e3 = e2 * t[2];
        const float w0 = alpha[0] * E;
        const float w1 = alpha[1] * e1;
        const float w2 = alpha[2] * e2;
        const float w3 = alpha[3] * e3;

        *(float4*)(out_w + (size_t)ray * 128 + lane * 4) = make_float4(w0, w1, w2, w3);

        // ---- packed tanh; accumulate raw tanh dot-products ----
        const __half2 hx0 = h2_tanh(__floats2half2_rn(0.5f * pt[0].x, 0.5f * pt[1].x));
        const __half2 hy0 = h2_tanh(__floats2half2_rn(0.5f * pt[0].y, 0.5f * pt[1].y));
        const __half2 hz0 = h2_tanh(__floats2half2_rn(0.5f * pt[0].z, 0.5f * pt[1].z));
        const __half2 hx1 = h2_tanh(__floats2half2_rn(0.5f * pt[2].x, 0.5f * pt[3].x));
        const __half2 hy1 = h2_tanh(__floats2half2_rn(0.5f * pt[2].y, 0.5f * pt[3].y));
        const __half2 hz1 = h2_tanh(__floats2half2_rn(0.5f * pt[2].z, 0.5f * pt[3].z));

        float ar = fmaf(w0, __low2float (hx0),
                   fmaf(w1, __high2float(hx0),
                   fmaf(w2, __low2float (hx1), w3 * __high2float(hx1))));
        float ag = fmaf(w0, __low2float (hy0),
                   fmaf(w1, __high2float(hy0),
                   fmaf(w2, __low2float (hy1), w3 * __high2float(hy1))));
        float ab = fmaf(w0, __low2float (hz0),
                   fmaf(w1, __high2float(hz0),
                   fmaf(w2, __low2float (hz1), w3 * __high2float(hz1))));
        float ad = fmaf(w0, zloc[0], fmaf(w1, zloc[1], fmaf(w2, zloc[2], w3 * zloc[3])));

        // ---- 4 warp tree-reduces (aa comes free from the scan total) ----
#pragma unroll
        for (int off = 16; off >= 1; off >>= 1) {
            ar += __shfl_xor_sync(FULL, ar, off);
            ag += __shfl_xor_sync(FULL, ag, off);
            ab += __shfl_xor_sync(FULL, ab, off);
            ad += __shfl_xor_sync(FULL, ad, off);
        }

        // alpha_map = sum w = 1 - prod(all t)   (+eps*sum(T) ~ 1e-8, dropped)
        const float aa = 1.0f - Ptot;

        if (lane == 0) {
            // fold sigma = 0.5*tanh + 0.5
            float cr = fmaf(0.5f, ar, 0.5f * aa);
            float cg = fmaf(0.5f, ag, 0.5f * aa);
            float cb = fmaf(0.5f, ab, 0.5f * aa);

            if (is_bg) {
                const float m = 1.0f - aa;
                cr = fmaf(m, b0, cr);
                cg = fmaf(m, b1, cg);
                cb = fmaf(m, b2, cb);
            }
            out_rgb[ray * 3 + 0] = cr;
            out_rgb[ray * 3 + 1] = cg;
            out_rgb[ray * 3 + 2] = cb;
            out_depth[ray] = ad;
            out_alpha[ray] = aa;

            const float q = ad / aa;
            out_disp[ray] = 1.0f / (fmaxf(q - EPSV, 0.0f) + EPSV);
        }

        // ---- rotate pipeline ----
        zc   = zn_c;
        nrmc = nrmn;
        buf ^= 1;
    }
}

extern "C" void kernel_launch(void* const* d_in, const int* in_sizes, int n_in,
                              void* d_out, int out_size)
{
    const float* raw = (const float*)d_in[0];  // (B,R,P,4)
    const float* zv  = (const float*)d_in[1];  // (B,R,P)
    const float* rd  = (const float*)d_in[2];  // (B,R,3)
    const float* bg  = (const float*)d_in[3];  // (3)

    const int nrays = in_sizes[1] / 128;       // B*R

    float* out       = (float*)d_out;
    float* out_rgb   = out;
    float* out_depth = out + (size_t)nrays * 3;
    float* out_disp  = out + (size_t)nrays * 4;
    float* out_alpha = out + (size_t)nrays * 5;
    float* out_w     = out + (size_t)nrays * 6;

    int blocks = 148 * 12;                     // 2 resident waves @ 6 blocks/SM
    const int maxblk = (nrays + 7) / 8;
    if (blocks > maxblk) blocks = maxblk;
    nerf_agg_kernel<<<blocks, 256>>>((const float4*)raw, zv, rd, bg,
                                     out_rgb, out_depth, out_disp, out_alpha,
                                     out_w, nrays);
}

// round 16
// speedup vs baseline: 1.2894x; 1.0104x over previous
#include <cuda_runtime.h>
#include <cuda_fp16.h>

// NeRF volume-rendering aggregation — R16.
// Occupancy axis fully swept: R7 (57 regs, 4 blocks/SM, grid 1184, depth-2
// cp.async) is the measured optimum (32.9us kernel). R16 = R7 verbatim plus
// the only two individually-verified-neutral work cuts:
//  - alpha_map telescoped: sum(w) = 1 - prod(all t) (one whole warp-reduce
//    deleted; rel_err unchanged at 5.2519e-5 in R13/R14)
//  - bg loads + is_bg test hoisted out of the ray loop
// NO launch_bounds min-blocks clause: reg cap to 40 cost more than it bought.

#define FARV 1e10f
#define EPSV 1e-10f
#define FULL 0xffffffffu

__device__ __forceinline__ __half2 h2_tanh(__half2 x) {
    __half2 r;
    asm("tanh.approx.f16x2 %0, %1;" : "=r"(*(unsigned*)&r) : "r"(*(unsigned*)&x));
    return r;
}

// XOR-swizzle byte offset within a 2048B tile.
__device__ __forceinline__ unsigned swz(unsigned a) {
    return a ^ ((a >> 3) & 0x30u);
}

__device__ __forceinline__ void cpasync16(unsigned dst, const void* src) {
    asm volatile("cp.async.cg.shared.global [%0], [%1], 16;" :: "r"(dst), "l"(src));
}
__device__ __forceinline__ void cpcommit() {
    asm volatile("cp.async.commit_group;");
}
__device__ __forceinline__ void cpwait1() {
    asm volatile("cp.async.wait_group 1;");
}

__global__ __launch_bounds__(256) void nerf_agg_kernel(
    const float4* __restrict__ raw,    // (NR, 128) of float4
    const float*  __restrict__ z,      // (NR, 128)
    const float*  __restrict__ rays_d, // (NR, 3)
    const float*  __restrict__ bg,     // (3)
    float* __restrict__ out_rgb,       // (NR, 3)
    float* __restrict__ out_depth,     // (NR)
    float* __restrict__ out_disp,      // (NR)
    float* __restrict__ out_alpha,     // (NR)
    float* __restrict__ out_w,         // (NR, 128)
    int nrays)
{
    __shared__ __align__(128) char sbuf[8 * 2 * 2048];  // per-warp double buffer

    const int warp = threadIdx.x >> 5;
    const int lane = threadIdx.x & 31;
    char* swp = sbuf + warp * 4096;
    const unsigned swb = (unsigned)__cvta_generic_to_shared(swp);

    const int gw = blockIdx.x * 8 + warp;     // global warp id
    const int W  = gridDim.x * 8;             // total warps (stride)
    if (gw >= nrays) return;                  // warp-uniform

    // loop-invariant background state
    const float b0 = bg[0], b1 = bg[1], b2 = bg[2];
    const bool is_bg = (b0 >= 0.f && b0 <= 1.f &&
                        b1 >= 0.f && b1 <= 1.f &&
                        b2 >= 0.f && b2 <= 1.f);

    // ---- prologue: prefetch ray gw into buffer 0; z/norm into registers ----
    {
        const float4* rawr = raw + (size_t)gw * 128;
#pragma unroll
        for (int rr = 0; rr < 4; rr++)
            cpasync16(swb + swz((rr * 32 + lane) * 16u), rawr + rr * 32 + lane);
        cpcommit();
    }
    float4 zc = *(const float4*)(z + (size_t)gw * 128 + lane * 4);
    float nrmc;
    {
        const float a = rays_d[gw * 3 + 0];
        const float b = rays_d[gw * 3 + 1];
        const float c = rays_d[gw * 3 + 2];
        nrmc = sqrtf(a * a + b * b + c * c);
    }

    int buf = 0;
    for (int ray = gw; ray < nrays; ray += W) {
        // ---- prefetch next ray (flies during this ray's compute) ----
        const int nray = ray + W;
        float4 zn_c = zc;
        float  nrmn = nrmc;
        if (nray < nrays) {         // warp-uniform branch
            const float4* rawr = raw + (size_t)nray * 128;
            const unsigned d = swb + (unsigned)(buf ^ 1) * 2048u;
#pragma unroll
            for (int rr = 0; rr < 4; rr++)
                cpasync16(d + swz((rr * 32 + lane) * 16u), rawr + rr * 32 + lane);
            zn_c = *(const float4*)(z + (size_t)nray * 128 + lane * 4);
            const float a = rays_d[nray * 3 + 0];
            const float b = rays_d[nray * 3 + 1];
            const float c = rays_d[nray * 3 + 2];
            nrmn = sqrtf(a * a + b * b + c * c);
        }
        cpcommit();                 // one group per iteration (may be empty)
        cpwait1();                  // current buffer's group complete
        __syncwarp();

        // ---- read transposed points from smem ----
        char* d = swp + buf * 2048;
        float4 pt[4];
#pragma unroll
        for (int i = 0; i < 4; i++)
            pt[i] = *(const float4*)(d + swz((lane * 4 + i) * 16u));

        const float4 z4 = zc;
        const float  nrm = nrmc;

        // ---- z neighbors: lane-local except the lane boundary ----
        const float zb = __shfl_down_sync(FULL, z4.x, 1);    // z[lane*4+4]
        const float zloc[4] = { z4.x, z4.y, z4.z, z4.w };
        const float znxt[4] = { z4.y, z4.z, z4.w, zb };

        // ---- alpha + transmittance factors (f32 EX2) ----
        float alpha[4], t[4];
#pragma unroll
        for (int i = 0; i < 4; i++) {
            float dd = znxt[i] - zloc[i];
            if (i == 3 && lane == 31) dd = FARV;             // p == 127
            dd *= nrm;
            const float ex = __expf(-fmaxf(pt[i].w, 0.0f) * dd);
            alpha[i] = 1.0f - ex;
            t[i]     = ex + EPSV;                            // 1 - alpha + EPS
        }

        // ---- single warp scan over local products ----
        float S = (t[0] * t[1]) * (t[2] * t[3]);
#pragma unroll
        for (int off = 1; off < 32; off <<= 1) {
            const float v = __shfl_up_sync(FULL, S, off);
            S = (lane >= off) ? S * v : S;
        }
        const float Ptot = __shfl_sync(FULL, S, 31);         // product of ALL 128 t
        float E = __shfl_up_sync(FULL, S, 1);                // exclusive lane prefix
        if (lane == 0) E = 1.0f;

        const float e1 = E  * t[0];
        const float e2 = e1 * t[1];
        const float e3 = e2 * t[2];
        const float w0 = alpha[0] * E;
        const float w1 = alpha[1] * e1;
        const float w2 = alpha[2] * e2;
        const float w3 = alpha[3] * e3;

        *(float4*)(out_w + (size_t)ray * 128 + lane * 4) = make_float4(w0, w1, w2, w3);

        // ---- packed tanh; accumulate raw tanh dot-products ----
        const __half2 hx0 = h2_tanh(__floats2half2_rn(0.5f * pt[0].x, 0.5f * pt[1].x));
        const __half2 hy0 = h2_tanh(__floats2half2_rn(0.5f * pt[0].y, 0.5f * pt[1].y));
        const __half2 hz0 = h2_tanh(__floats2half2_rn(0.5f * pt[0].z, 0.5f * pt[1].z));
        const __half2 hx1 = h2_tanh(__floats2half2_rn(0.5f * pt[2].x, 0.5f * pt[3].x));
        const __half2 hy1 = h2_tanh(__floats2half2_rn(0.5f * pt[2].y, 0.5f * pt[3].y));
        const __half2 hz1 = h2_tanh(__floats2half2_rn(0.5f * pt[2].z, 0.5f * pt[3].z));

        float ar = fmaf(w0, __low2float (hx0),
                   fmaf(w1, __high2float(hx0),
                   fmaf(w2, __low2float (hx1), w3 * __high2float(hx1))));
        float ag = fmaf(w0, __low2float (hy0),
                   fmaf(w1, __high2float(hy0),
                   fmaf(w2, __low2float (hy1), w3 * __high2float(hy1))));
        float ab = fmaf(w0, __low2float (hz0),
                   fmaf(w1, __high2float(hz0),
                   fmaf(w2, __low2float (hz1), w3 * __high2float(hz1))));
        float ad = fmaf(w0, zloc[0], fmaf(w1, zloc[1], fmaf(w2, zloc[2], w3 * zloc[3])));

        // ---- 4 warp tree-reduces (aa comes free from the scan total) ----
#pragma unroll
        for (int off = 16; off >= 1; off >>= 1) {
            ar += __shfl_xor_sync(FULL, ar, off);
            ag += __shfl_xor_sync(FULL, ag, off);
            ab += __shfl_xor_sync(FULL, ab, off);
            ad += __shfl_xor_sync(FULL, ad, off);
        }

        // alpha_map = sum w = 1 - prod(all t)   (+eps*sum(T) ~ 1e-8, dropped)
        const float aa = 1.0f - Ptot;

        if (lane == 0) {
            // fold sigma = 0.5*tanh + 0.5
            float cr = fmaf(0.5f, ar, 0.5f * aa);
            float cg = fmaf(0.5f, ag, 0.5f * aa);
            float cb = fmaf(0.5f, ab, 0.5f * aa);

            if (is_bg) {
                const float m = 1.0f - aa;
                cr = fmaf(m, b0, cr);
                cg = fmaf(m, b1, cg);
                cb = fmaf(m, b2, cb);
            }
            out_rgb[ray * 3 + 0] = cr;
            out_rgb[ray * 3 + 1] = cg;
            out_rgb[ray * 3 + 2] = cb;
            out_depth[ray] = ad;
            out_alpha[ray] = aa;

            const float q = ad / aa;
            out_disp[ray] = 1.0f / (fmaxf(q - EPSV, 0.0f) + EPSV);
        }

        // ---- rotate pipeline ----
        zc   = zn_c;
        nrmc = nrmn;
        buf ^= 1;
    }
}

extern "C" void kernel_launch(void* const* d_in, const int* in_sizes, int n_in,
                              void* d_out, int out_size)
{
    const float* raw = (const float*)d_in[0];  // (B,R,P,4)
    const float* zv  = (const float*)d_in[1];  // (B,R,P)
    const float* rd  = (const float*)d_in[2];  // (B,R,3)
    const float* bg  = (const float*)d_in[3];  // (3)

    const int nrays = in_sizes[1] / 128;       // B*R

    float* out       = (float*)d_out;
    float* out_rgb   = out;
    float* out_depth = out + (size_t)nrays * 3;
    float* out_disp  = out + (size_t)nrays * 4;
    float* out_alpha = out + (size_t)nrays * 5;
    float* out_w     = out + (size_t)nrays * 6;

    int blocks = 148 * 8;                      // R7's measured-optimal config
    const int maxblk = (nrays + 7) / 8;
    if (blocks > maxblk) blocks = maxblk;
    nerf_agg_kernel<<<blocks, 256>>>((const float4*)raw, zv, rd, bg,
                                     out_rgb, out_depth, out_disp, out_alpha,
                                     out_w, nrays);
}